// round 12
// baseline (speedup 1.0000x reference)
#include <cuda_runtime.h>

// SOM batch_train, 8192 sequential steps. Persistent 64-CTA kernel:
// 16 neuron warps + 1 comm warp per CTA (544 thr).
// R12 delta vs R11 (8216us): shorten the detect->store serial chain.
//  (1) comm pre-loads ABV into registers BEFORE the L2 poll (neuron warps
//      signal ABV readiness via smem flags; volatile + threadfence_block);
//  (2) candidate store issues BEFORE sm_c write and __syncthreads, removing
//      both from the inter-CTA critical chain.
// Inter-CTA protocol (relaxed atomics, RING=4 tags, handshake) is identical
// to the passing R11.
//
//   d2_{t+1} = A - 2cB + c^2 V,  u=x_{t+1}-w_t, v=x_t-w_t, A=|u|^2,B=<u,v>,V=|v|^2
// All sums fresh each step (no drift). sm_c/sm_ABV double-buffered by parity.

#define DIM      384
#define KREG     12           // DIM / 32 dims per lane
#define NCTA     64
#define NPC      16           // neurons per CTA
#define NTHREADS 544          // 16 neuron warps + 1 comm warp
#define RING     4
#define SLOT_STRIDE 16        // u64 per slot -> one 128B line per CTA slot

// packed (d2bits:32 | tag:22 | neuron:10); zero at load, re-zeroed each launch
__device__ unsigned long long g_slots[RING][NCTA * SLOT_STRIDE];

static __device__ __forceinline__ unsigned long long ld_rlx(const unsigned long long* p) {
    unsigned long long v;
    asm volatile("ld.relaxed.gpu.global.b64 %0, [%1];" : "=l"(v) : "l"(p) : "memory");
    return v;
}
static __device__ __forceinline__ void st_rlx(unsigned long long* p, unsigned long long v) {
    asm volatile("st.relaxed.gpu.global.b64 [%0], %1;" :: "l"(p), "l"(v) : "memory");
}

__global__ void __launch_bounds__(NTHREADS, 1)
som_kernel(const float* __restrict__ X, const float* __restrict__ W0,
           const int* __restrict__ ep, float* __restrict__ out, int n_samples)
{
    const int cta  = blockIdx.x;
    const int tid  = threadIdx.x;
    const int warp = tid >> 5;
    const int lane = tid & 31;

    int epochs = *ep;
    if (epochs < 1 || epochs > 8) epochs = 1;
    const int TS = epochs * n_samples;           // <= 65536, tags fit 22 bits

    __shared__ float c_table[63 * 63];           // 0.1*exp(-0.5*sqrt(dx^2+dy^2))
    __shared__ float4 sm_ABV[2][NPC];            // (A, -2B, V), parity-buffered
    __shared__ float sm_c[2][NPC];               // per-neuron c, parity-buffered
    __shared__ volatile int sm_flag[NPC];        // ABV-ready tag per neuron warp
    __shared__ unsigned long long sm_pack[NPC];  // prologue only

    for (int i = tid; i < 63 * 63; i += NTHREADS) {
        float dx = (float)(i / 63 - 31);
        float dy = (float)(i % 63 - 31);
        c_table[i] = 0.1f * expf(-0.5f * sqrtf(dx * dx + dy * dy));
    }
    if (tid < NPC) { sm_c[1][tid] = 0.f; sm_flag[tid] = 0; }

    // ---- neuron-warp state ----
    const int n = cta * NPC + warp;              // valid for warp < 16
    float w[KREG], v[KREG], u[KREG], xn[KREG];
    int pf = (n_samples > 2) ? 2 : (2 % n_samples);

    if (warp < NPC) {
        float a0 = 0.f, a1 = 0.f, a2 = 0.f, a3 = 0.f;
#pragma unroll
        for (int k = 0; k < KREG; k++) {
            float wk = W0[n * DIM + lane + 32 * k];
            w[k] = wk;
            v[k] = 0.f;
            float t0 = X[lane + 32 * k] - wk;    // u = x0 - w0
            u[k] = t0;
            if ((k & 3) == 0) a0 = fmaf(t0, t0, a0);
            else if ((k & 3) == 1) a1 = fmaf(t0, t0, a1);
            else if ((k & 3) == 2) a2 = fmaf(t0, t0, a2);
            else a3 = fmaf(t0, t0, a3);
        }
        float d2 = (a0 + a1) + (a2 + a3);
#pragma unroll
        for (int off = 16; off; off >>= 1)
            d2 += __shfl_xor_sync(0xFFFFFFFFu, d2, off);
#pragma unroll
        for (int k = 0; k < KREG; k++) xn[k] = X[DIM + lane + 32 * k];   // x1

        if (lane == 0)
            sm_pack[warp] = ((unsigned long long)__float_as_uint(d2) << 32)
                          | ((1u << 10) | (unsigned)n);
    }

    __syncthreads();                             // packs + sm_c[1] + flags + LUT

    if (warp == NPC) {                           // store candidate(0), tag 1
        unsigned long long p = (lane < NPC) ? sm_pack[lane] : 0xFFFFFFFFFFFFFFFFull;
        unsigned phi = (unsigned)(p >> 32), plo = (unsigned)p;
        unsigned mhi = __reduce_min_sync(0xFFFFFFFFu, phi);
        unsigned cnd = (phi == mhi) ? plo : 0xFFFFFFFFu;
        unsigned mlo = __reduce_min_sync(0xFFFFFFFFu, cnd);
        if (lane == 0)
            st_rlx(&g_slots[0][cta * SLOT_STRIDE],
                   ((unsigned long long)mhi << 32) | mlo);
    }

    const int nl = cta * NPC + (lane & 15);      // comm-lane neuron id (in range)
    const int lut_base = (nl >> 5) * 63 + (nl & 31) + (31 * 63 + 31);

    for (int t = 0; t < TS; ++t) {
        const int par = t & 1;

        if (warp == NPC) {
            // ---- (a) wait for neuron ABV(t), frontload into registers ----
            {
                bool ok;
                do {
                    ok = (lane >= NPC) || (sm_flag[lane] == t + 1);
                } while (!__all_sync(0xFFFFFFFFu, ok));
            }
            __threadfence_block();
            const float4 q = sm_ABV[par][lane & 15];      // (A, -2B, V)

            // ---- (b) pipelined L2 poll for bmu(t) ----
            const unsigned tag = (unsigned)(t + 1) & 0x3FFFFFu;
            const int ring = t & (RING - 1);
            unsigned long long* p0 = &g_slots[ring][lane * SLOT_STRIDE];
            unsigned long long* p1 = &g_slots[ring][(lane + 32) * SLOT_STRIDE];
            unsigned long long v0, v1;
            for (;;) {
                unsigned long long a0 = ld_rlx(p0), a1 = ld_rlx(p1);
                unsigned long long b0 = ld_rlx(p0), b1 = ld_rlx(p1);
                bool oka = ((((unsigned)a0) >> 10) == tag) &&
                           ((((unsigned)a1) >> 10) == tag);
                if (__all_sync(0xFFFFFFFFu, oka)) { v0 = a0; v1 = a1; break; }
                bool okb = ((((unsigned)b0) >> 10) == tag) &&
                           ((((unsigned)b1) >> 10) == tag);
                if (__all_sync(0xFFFFFFFFu, okb)) { v0 = b0; v1 = b1; break; }
            }
            unsigned long long vm = (v0 < v1) ? v0 : v1;
            unsigned qhi = (unsigned)(vm >> 32), qlo = (unsigned)vm;
            unsigned gh = __reduce_min_sync(0xFFFFFFFFu, qhi);
            unsigned gc = (qhi == gh) ? qlo : 0xFFFFFFFFu;
            unsigned gl = __reduce_min_sync(0xFFFFFFFFu, gc);
            const int bmu = (int)(gl & 0x3FFu);

            // ---- (c) critical tail: c, d2(t+1), CTA argmin, STORE FIRST ----
            const float ci = c_table[lut_base - (bmu >> 5) * 63 - (bmu & 31)];
            if (t + 1 < TS) {
                float d2 = fmaxf(fmaf(ci, fmaf(ci, q.z, q.y), q.x), 0.f);
                unsigned tag2 = (unsigned)(t + 2) & 0x3FFFFFu;
                unsigned long long pk = (lane < NPC)
                    ? (((unsigned long long)__float_as_uint(d2) << 32)
                       | ((tag2 << 10) | (unsigned)nl))
                    : 0xFFFFFFFFFFFFFFFFull;
                unsigned phi = (unsigned)(pk >> 32), plo = (unsigned)pk;
                unsigned mhi = __reduce_min_sync(0xFFFFFFFFu, phi);
                unsigned cnd = (phi == mhi) ? plo : 0xFFFFFFFFu;
                unsigned mlo = __reduce_min_sync(0xFFFFFFFFu, cnd);
                if (lane == 0)
                    st_rlx(&g_slots[(t + 1) & (RING - 1)][cta * SLOT_STRIDE],
                           ((unsigned long long)mhi << 32) | mlo);
            }
            // ---- (d) off-chain: publish c for neurons, join barrier ----
            if (lane < NPC) sm_c[par][lane] = ci;
        } else {
            // ======== neurons: window work (poll shadow) ========
            const float cp = sm_c[par ^ 1][warp];    // c(t-1), sync(t-1)-ordered
#pragma unroll
            for (int k = 0; k < KREG; k++) {
                float vo = v[k];
                w[k] = fmaf(cp, vo, w[k]);
                v[k] = fmaf(-cp, vo, u[k]);
                u[k] = xn[k] - w[k];
            }
            const float* xp = X + (size_t)pf * DIM + lane;   // prefetch x(t+2)
#pragma unroll
            for (int k = 0; k < KREG; k++) xn[k] = xp[32 * k];
            pf++; if (pf == n_samples) pf = 0;

            float a0 = 0.f, a1 = 0.f, b0 = 0.f, b1 = 0.f, q0 = 0.f, q1 = 0.f;
#pragma unroll
            for (int k = 0; k < KREG; k += 2) {
                a0 = fmaf(u[k + 0], u[k + 0], a0); b0 = fmaf(u[k + 0], v[k + 0], b0);
                q0 = fmaf(v[k + 0], v[k + 0], q0);
                a1 = fmaf(u[k + 1], u[k + 1], a1); b1 = fmaf(u[k + 1], v[k + 1], b1);
                q1 = fmaf(v[k + 1], v[k + 1], q1);
            }
            float A = a0 + a1, B = b0 + b1, V = q0 + q1;
#pragma unroll
            for (int off = 16; off; off >>= 1) {
                A += __shfl_xor_sync(0xFFFFFFFFu, A, off);
                B += __shfl_xor_sync(0xFFFFFFFFu, B, off);
                V += __shfl_xor_sync(0xFFFFFFFFu, V, off);
            }
            if (lane == 0) {
                sm_ABV[par][warp] = make_float4(A, -2.f * B, V, 0.f);
                __threadfence_block();
                sm_flag[warp] = t + 1;               // ABV(t) ready
            }
        }

        __syncthreads();   // c(t) visible to neurons for iter t+1
    }

    if (warp < NPC) {
        // epilogue: apply final update c(TS-1), write weights
        const float cp = sm_c[(TS - 1) & 1][warp];
#pragma unroll
        for (int k = 0; k < KREG; k++)
            out[n * DIM + lane + 32 * k] = fmaf(cp, v[k], w[k]);
    } else {
        // ---- termination handshake + scratch cleanup (deterministic replays) ----
        // ring(TS&3) received no candidate store (skipped at t=TS-1), so the
        // handshake tag TS+1 is this slot's unique terminal value.
        const unsigned ftag = (unsigned)(TS + 1) & 0x3FFFFFu;
        const int fring = TS & (RING - 1);
        if (lane == 0)
            st_rlx(&g_slots[fring][cta * SLOT_STRIDE],
                   (unsigned long long)(ftag << 10));

        if (cta == 0) {
            for (;;) {
                unsigned long long v0 = ld_rlx(&g_slots[fring][lane * SLOT_STRIDE]);
                unsigned long long v1 = ld_rlx(&g_slots[fring][(lane + 32) * SLOT_STRIDE]);
                bool ok = ((((unsigned)v0) >> 10) == ftag) &&
                          ((((unsigned)v1) >> 10) == ftag);
                if (__all_sync(0xFFFFFFFFu, ok)) break;
            }
#pragma unroll
            for (int r = 0; r < RING; r++) {
                st_rlx(&g_slots[r][lane * SLOT_STRIDE], 0ull);
                st_rlx(&g_slots[r][(lane + 32) * SLOT_STRIDE], 0ull);
            }
            __threadfence();
        }
    }
}

extern "C" void kernel_launch(void* const* d_in, const int* in_sizes, int n_in,
                              void* d_out, int out_size)
{
    const float* X  = (const float*)d_in[0];   // [8192, 384]
    const float* W0 = (const float*)d_in[1];   // [32, 32, 384]
    const int*   ep = (const int*)d_in[3];     // num_epochs
    float* out = (float*)d_out;                // [32, 32, 384]

    int n_samples = in_sizes[0] / DIM;
    som_kernel<<<NCTA, NTHREADS>>>(X, W0, ep, out, n_samples);
}

// round 13
// speedup vs baseline: 1.3085x; 1.3085x over previous
#include <cuda_runtime.h>

// SOM batch_train, 8192 sequential steps. Persistent 64-CTA kernel:
// 16 neuron warps + 1 comm warp per CTA (544 thr).
// R13 = R11 structure (comm polls IMMEDIATELY after sync; neuron window work
// fully overlapped) + R12's tail shortening placed CORRECTLY: the ABV flag
// wait happens AFTER BMU detect (where it is ~free, neurons finished during
// the poll), so candidate store issues before sm_c STS and __syncthreads.
// R12's mistake was waiting for ABV BEFORE the poll, serializing neuron work
// with slot discovery (8216 -> 10628). Inter-CTA protocol unchanged.
//
//   d2_{t+1} = A - 2cB + c^2 V,  u=x_{t+1}-w_t, v=x_t-w_t, A=|u|^2,B=<u,v>,V=|v|^2
// All sums fresh each step (no drift). sm_c/sm_ABV double-buffered by parity.

#define DIM      384
#define KREG     12           // DIM / 32 dims per lane
#define NCTA     64
#define NPC      16           // neurons per CTA
#define NTHREADS 544          // 16 neuron warps + 1 comm warp
#define RING     4
#define SLOT_STRIDE 16        // u64 per slot -> one 128B line per CTA slot

// packed (d2bits:32 | tag:22 | neuron:10); zero at load, re-zeroed each launch
__device__ unsigned long long g_slots[RING][NCTA * SLOT_STRIDE];

static __device__ __forceinline__ unsigned long long ld_rlx(const unsigned long long* p) {
    unsigned long long v;
    asm volatile("ld.relaxed.gpu.global.b64 %0, [%1];" : "=l"(v) : "l"(p) : "memory");
    return v;
}
static __device__ __forceinline__ void st_rlx(unsigned long long* p, unsigned long long v) {
    asm volatile("st.relaxed.gpu.global.b64 [%0], %1;" :: "l"(p), "l"(v) : "memory");
}

__global__ void __launch_bounds__(NTHREADS, 1)
som_kernel(const float* __restrict__ X, const float* __restrict__ W0,
           const int* __restrict__ ep, float* __restrict__ out, int n_samples)
{
    const int cta  = blockIdx.x;
    const int tid  = threadIdx.x;
    const int warp = tid >> 5;
    const int lane = tid & 31;

    int epochs = *ep;
    if (epochs < 1 || epochs > 8) epochs = 1;
    const int TS = epochs * n_samples;           // <= 65536, tags fit 22 bits

    __shared__ float c_table[63 * 63];           // 0.1*exp(-0.5*sqrt(dx^2+dy^2))
    __shared__ float4 sm_ABV[2][NPC];            // (A, -2B, V), parity-buffered
    __shared__ float sm_c[2][NPC];               // per-neuron c, parity-buffered
    __shared__ volatile int sm_flag[NPC];        // ABV-ready tag per neuron warp
    __shared__ unsigned long long sm_pack[NPC];  // prologue only

    for (int i = tid; i < 63 * 63; i += NTHREADS) {
        float dx = (float)(i / 63 - 31);
        float dy = (float)(i % 63 - 31);
        c_table[i] = 0.1f * expf(-0.5f * sqrtf(dx * dx + dy * dy));
    }
    if (tid < NPC) { sm_c[1][tid] = 0.f; sm_flag[tid] = 0; }

    // ---- neuron-warp state ----
    const int n = cta * NPC + warp;              // valid for warp < 16
    float w[KREG], v[KREG], u[KREG], xn[KREG];
    int pf = (n_samples > 2) ? 2 : (2 % n_samples);

    if (warp < NPC) {
        float a0 = 0.f, a1 = 0.f, a2 = 0.f, a3 = 0.f;
#pragma unroll
        for (int k = 0; k < KREG; k++) {
            float wk = W0[n * DIM + lane + 32 * k];
            w[k] = wk;
            v[k] = 0.f;
            float t0 = X[lane + 32 * k] - wk;    // u = x0 - w0
            u[k] = t0;
            if ((k & 3) == 0) a0 = fmaf(t0, t0, a0);
            else if ((k & 3) == 1) a1 = fmaf(t0, t0, a1);
            else if ((k & 3) == 2) a2 = fmaf(t0, t0, a2);
            else a3 = fmaf(t0, t0, a3);
        }
        float d2 = (a0 + a1) + (a2 + a3);
#pragma unroll
        for (int off = 16; off; off >>= 1)
            d2 += __shfl_xor_sync(0xFFFFFFFFu, d2, off);
#pragma unroll
        for (int k = 0; k < KREG; k++) xn[k] = X[DIM + lane + 32 * k];   // x1

        if (lane == 0)
            sm_pack[warp] = ((unsigned long long)__float_as_uint(d2) << 32)
                          | ((1u << 10) | (unsigned)n);
    }

    __syncthreads();                             // packs + sm_c[1] + flags + LUT

    if (warp == NPC) {                           // store candidate(0), tag 1
        unsigned long long p = (lane < NPC) ? sm_pack[lane] : 0xFFFFFFFFFFFFFFFFull;
        unsigned phi = (unsigned)(p >> 32), plo = (unsigned)p;
        unsigned mhi = __reduce_min_sync(0xFFFFFFFFu, phi);
        unsigned cnd = (phi == mhi) ? plo : 0xFFFFFFFFu;
        unsigned mlo = __reduce_min_sync(0xFFFFFFFFu, cnd);
        if (lane == 0)
            st_rlx(&g_slots[0][cta * SLOT_STRIDE],
                   ((unsigned long long)mhi << 32) | mlo);
    }

    const int nl = cta * NPC + (lane & 15);      // comm-lane neuron id (in range)
    const int lut_base = (nl >> 5) * 63 + (nl & 31) + (31 * 63 + 31);

    for (int t = 0; t < TS; ++t) {
        const int par = t & 1;

        if (warp == NPC) {
            // ---- (a) pipelined L2 poll for bmu(t): starts IMMEDIATELY ----
            const unsigned tag = (unsigned)(t + 1) & 0x3FFFFFu;
            const int ring = t & (RING - 1);
            unsigned long long* p0 = &g_slots[ring][lane * SLOT_STRIDE];
            unsigned long long* p1 = &g_slots[ring][(lane + 32) * SLOT_STRIDE];
            unsigned long long v0, v1;
            for (;;) {
                unsigned long long a0 = ld_rlx(p0), a1 = ld_rlx(p1);
                unsigned long long b0 = ld_rlx(p0), b1 = ld_rlx(p1);
                bool oka = ((((unsigned)a0) >> 10) == tag) &&
                           ((((unsigned)a1) >> 10) == tag);
                if (__all_sync(0xFFFFFFFFu, oka)) { v0 = a0; v1 = a1; break; }
                bool okb = ((((unsigned)b0) >> 10) == tag) &&
                           ((((unsigned)b1) >> 10) == tag);
                if (__all_sync(0xFFFFFFFFu, okb)) { v0 = b0; v1 = b1; break; }
            }
            unsigned long long vm = (v0 < v1) ? v0 : v1;
            unsigned qhi = (unsigned)(vm >> 32), qlo = (unsigned)vm;
            unsigned gh = __reduce_min_sync(0xFFFFFFFFu, qhi);
            unsigned gc = (qhi == gh) ? qlo : 0xFFFFFFFFu;
            unsigned gl = __reduce_min_sync(0xFFFFFFFFu, gc);
            const int bmu = (int)(gl & 0x3FFu);

            // ---- (b) critical tail: c, then ABV (ready long ago), store ----
            const float ci = c_table[lut_base - (bmu >> 5) * 63 - (bmu & 31)];
            if (t + 1 < TS) {
                // flag wait is ~instant: neurons finished ABV during the poll
                bool ok;
                do {
                    ok = (lane >= NPC) || (sm_flag[lane] == t + 1);
                } while (!__all_sync(0xFFFFFFFFu, ok));
                __threadfence_block();
                const float4 q = sm_ABV[par][lane & 15];      // (A, -2B, V)
                float d2 = fmaxf(fmaf(ci, fmaf(ci, q.z, q.y), q.x), 0.f);
                unsigned tag2 = (unsigned)(t + 2) & 0x3FFFFFu;
                unsigned long long pk = (lane < NPC)
                    ? (((unsigned long long)__float_as_uint(d2) << 32)
                       | ((tag2 << 10) | (unsigned)nl))
                    : 0xFFFFFFFFFFFFFFFFull;
                unsigned phi2 = (unsigned)(pk >> 32), plo2 = (unsigned)pk;
                unsigned mhi2 = __reduce_min_sync(0xFFFFFFFFu, phi2);
                unsigned cnd2 = (phi2 == mhi2) ? plo2 : 0xFFFFFFFFu;
                unsigned mlo2 = __reduce_min_sync(0xFFFFFFFFu, cnd2);
                if (lane == 0)
                    st_rlx(&g_slots[(t + 1) & (RING - 1)][cta * SLOT_STRIDE],
                           ((unsigned long long)mhi2 << 32) | mlo2);
            }
            // ---- (c) off-chain: publish c for neurons, join barrier ----
            if (lane < NPC) sm_c[par][lane] = ci;
        } else {
            // ======== neurons: window work (poll shadow) ========
            const float cp = sm_c[par ^ 1][warp];    // c(t-1), sync(t-1)-ordered
#pragma unroll
            for (int k = 0; k < KREG; k++) {
                float vo = v[k];
                w[k] = fmaf(cp, vo, w[k]);
                v[k] = fmaf(-cp, vo, u[k]);
                u[k] = xn[k] - w[k];
            }
            const float* xp = X + (size_t)pf * DIM + lane;   // prefetch x(t+2)
#pragma unroll
            for (int k = 0; k < KREG; k++) xn[k] = xp[32 * k];
            pf++; if (pf == n_samples) pf = 0;

            float a0 = 0.f, a1 = 0.f, b0 = 0.f, b1 = 0.f, q0 = 0.f, q1 = 0.f;
#pragma unroll
            for (int k = 0; k < KREG; k += 2) {
                a0 = fmaf(u[k + 0], u[k + 0], a0); b0 = fmaf(u[k + 0], v[k + 0], b0);
                q0 = fmaf(v[k + 0], v[k + 0], q0);
                a1 = fmaf(u[k + 1], u[k + 1], a1); b1 = fmaf(u[k + 1], v[k + 1], b1);
                q1 = fmaf(v[k + 1], v[k + 1], q1);
            }
            float A = a0 + a1, B = b0 + b1, V = q0 + q1;
#pragma unroll
            for (int off = 16; off; off >>= 1) {
                A += __shfl_xor_sync(0xFFFFFFFFu, A, off);
                B += __shfl_xor_sync(0xFFFFFFFFu, B, off);
                V += __shfl_xor_sync(0xFFFFFFFFu, V, off);
            }
            if (lane == 0) {
                sm_ABV[par][warp] = make_float4(A, -2.f * B, V, 0.f);
                __threadfence_block();
                sm_flag[warp] = t + 1;               // ABV(t) ready
            }
        }

        __syncthreads();   // c(t) visible to neurons for iter t+1
    }

    if (warp < NPC) {
        // epilogue: apply final update c(TS-1), write weights
        const float cp = sm_c[(TS - 1) & 1][warp];
#pragma unroll
        for (int k = 0; k < KREG; k++)
            out[n * DIM + lane + 32 * k] = fmaf(cp, v[k], w[k]);
    } else {
        // ---- termination handshake + scratch cleanup (deterministic replays) ----
        // ring(TS&3) received no candidate store (skipped at t=TS-1), so the
        // handshake tag TS+1 is this slot's unique terminal value.
        const unsigned ftag = (unsigned)(TS + 1) & 0x3FFFFFu;
        const int fring = TS & (RING - 1);
        if (lane == 0)
            st_rlx(&g_slots[fring][cta * SLOT_STRIDE],
                   (unsigned long long)(ftag << 10));

        if (cta == 0) {
            for (;;) {
                unsigned long long v0 = ld_rlx(&g_slots[fring][lane * SLOT_STRIDE]);
                unsigned long long v1 = ld_rlx(&g_slots[fring][(lane + 32) * SLOT_STRIDE]);
                bool ok = ((((unsigned)v0) >> 10) == ftag) &&
                          ((((unsigned)v1) >> 10) == ftag);
                if (__all_sync(0xFFFFFFFFu, ok)) break;
            }
#pragma unroll
            for (int r = 0; r < RING; r++) {
                st_rlx(&g_slots[r][lane * SLOT_STRIDE], 0ull);
                st_rlx(&g_slots[r][(lane + 32) * SLOT_STRIDE], 0ull);
            }
            __threadfence();
        }
    }
}

extern "C" void kernel_launch(void* const* d_in, const int* in_sizes, int n_in,
                              void* d_out, int out_size)
{
    const float* X  = (const float*)d_in[0];   // [8192, 384]
    const float* W0 = (const float*)d_in[1];   // [32, 32, 384]
    const int*   ep = (const int*)d_in[3];     // num_epochs
    float* out = (float*)d_out;                // [32, 32, 384]

    int n_samples = in_sizes[0] / DIM;
    som_kernel<<<NCTA, NTHREADS>>>(X, W0, ep, out, n_samples);
}

// round 14
// speedup vs baseline: 1.3149x; 1.0048x over previous
#include <cuda_runtime.h>

// SOM batch_train, 8192 sequential steps. Persistent 64-CTA kernel:
// 16 neuron warps + 1 comm warp per CTA (544 thr).
// R14 delta vs R13 (8122us): (1) NO __syncthreads in the steady-state loop --
// both intra-CTA handoffs are flag-based (volatile + threadfence_block), so
// comm goes store -> next poll with no 17-warp barrier release on the chain;
// (2) slot ring packed (stride 1): poll loads coalesce into 4 cache lines.
// Inter-CTA protocol (relaxed atomics, RING=4 tags, handshake) is identical
// to the passing R13. Handoff safety: comm's detect(t) transitively requires
// every local neuron warp's iter t-1 reads (via sm_flag==t before store(t)),
// so no parity-buffer write can race a straggling read.
//
//   d2_{t+1} = A - 2cB + c^2 V,  u=x_{t+1}-w_t, v=x_t-w_t, A=|u|^2,B=<u,v>,V=|v|^2
// All sums fresh each step (no drift). sm_c/sm_ABV double-buffered by parity.

#define DIM      384
#define KREG     12           // DIM / 32 dims per lane
#define NCTA     64
#define NPC      16           // neurons per CTA
#define NTHREADS 544          // 16 neuron warps + 1 comm warp
#define RING     4

// packed (d2bits:32 | tag:22 | neuron:10); zero at load, re-zeroed each launch
__device__ unsigned long long g_slots[RING][NCTA];

static __device__ __forceinline__ unsigned long long ld_rlx(const unsigned long long* p) {
    unsigned long long v;
    asm volatile("ld.relaxed.gpu.global.b64 %0, [%1];" : "=l"(v) : "l"(p) : "memory");
    return v;
}
static __device__ __forceinline__ void st_rlx(unsigned long long* p, unsigned long long v) {
    asm volatile("st.relaxed.gpu.global.b64 [%0], %1;" :: "l"(p), "l"(v) : "memory");
}

__global__ void __launch_bounds__(NTHREADS, 1)
som_kernel(const float* __restrict__ X, const float* __restrict__ W0,
           const int* __restrict__ ep, float* __restrict__ out, int n_samples)
{
    const int cta  = blockIdx.x;
    const int tid  = threadIdx.x;
    const int warp = tid >> 5;
    const int lane = tid & 31;

    int epochs = *ep;
    if (epochs < 1 || epochs > 8) epochs = 1;
    const int TS = epochs * n_samples;           // <= 65536, tags fit 22 bits

    __shared__ float c_table[63 * 63];           // 0.1*exp(-0.5*sqrt(dx^2+dy^2))
    __shared__ float4 sm_ABV[2][NPC];            // (A, -2B, V), parity-buffered
    __shared__ float sm_c[2][NPC];               // per-neuron c, parity-buffered
    __shared__ volatile int sm_flag[NPC];        // ABV-ready tag per neuron warp
    __shared__ volatile int sm_cflag;            // c-ready tag from comm warp
    __shared__ unsigned long long sm_pack[NPC];  // prologue only

    for (int i = tid; i < 63 * 63; i += NTHREADS) {
        float dx = (float)(i / 63 - 31);
        float dy = (float)(i % 63 - 31);
        c_table[i] = 0.1f * expf(-0.5f * sqrtf(dx * dx + dy * dy));
    }
    if (tid < NPC) { sm_c[1][tid] = 0.f; sm_flag[tid] = 0; }
    if (tid == 0) sm_cflag = 0;

    // ---- neuron-warp state ----
    const int n = cta * NPC + warp;              // valid for warp < 16
    float w[KREG], v[KREG], u[KREG], xn[KREG];
    int pf = (n_samples > 2) ? 2 : (2 % n_samples);

    if (warp < NPC) {
        float a0 = 0.f, a1 = 0.f, a2 = 0.f, a3 = 0.f;
#pragma unroll
        for (int k = 0; k < KREG; k++) {
            float wk = W0[n * DIM + lane + 32 * k];
            w[k] = wk;
            v[k] = 0.f;
            float t0 = X[lane + 32 * k] - wk;    // u = x0 - w0
            u[k] = t0;
            if ((k & 3) == 0) a0 = fmaf(t0, t0, a0);
            else if ((k & 3) == 1) a1 = fmaf(t0, t0, a1);
            else if ((k & 3) == 2) a2 = fmaf(t0, t0, a2);
            else a3 = fmaf(t0, t0, a3);
        }
        float d2 = (a0 + a1) + (a2 + a3);
#pragma unroll
        for (int off = 16; off; off >>= 1)
            d2 += __shfl_xor_sync(0xFFFFFFFFu, d2, off);
#pragma unroll
        for (int k = 0; k < KREG; k++) xn[k] = X[DIM + lane + 32 * k];   // x1

        if (lane == 0)
            sm_pack[warp] = ((unsigned long long)__float_as_uint(d2) << 32)
                          | ((1u << 10) | (unsigned)n);
    }

    __syncthreads();     // prologue only: packs + sm_c[1] + flags + LUT visible

    if (warp == NPC) {                           // store candidate(0), tag 1
        unsigned long long p = (lane < NPC) ? sm_pack[lane] : 0xFFFFFFFFFFFFFFFFull;
        unsigned phi = (unsigned)(p >> 32), plo = (unsigned)p;
        unsigned mhi = __reduce_min_sync(0xFFFFFFFFu, phi);
        unsigned cnd = (phi == mhi) ? plo : 0xFFFFFFFFu;
        unsigned mlo = __reduce_min_sync(0xFFFFFFFFu, cnd);
        if (lane == 0)
            st_rlx(&g_slots[0][cta], ((unsigned long long)mhi << 32) | mlo);
    }

    const int nl = cta * NPC + (lane & 15);      // comm-lane neuron id (in range)
    const int lut_base = (nl >> 5) * 63 + (nl & 31) + (31 * 63 + 31);

    if (warp == NPC) {
        // =================== comm warp: whole loop ===================
        for (int t = 0; t < TS; ++t) {
            const int par = t & 1;

            // ---- (a) pipelined, coalesced L2 poll for bmu(t) ----
            const unsigned tag = (unsigned)(t + 1) & 0x3FFFFFu;
            const int ring = t & (RING - 1);
            unsigned long long* p0 = &g_slots[ring][lane];
            unsigned long long* p1 = &g_slots[ring][lane + 32];
            unsigned long long v0, v1;
            for (;;) {
                unsigned long long a0 = ld_rlx(p0), a1 = ld_rlx(p1);
                unsigned long long b0 = ld_rlx(p0), b1 = ld_rlx(p1);
                bool oka = ((((unsigned)a0) >> 10) == tag) &&
                           ((((unsigned)a1) >> 10) == tag);
                if (__all_sync(0xFFFFFFFFu, oka)) { v0 = a0; v1 = a1; break; }
                bool okb = ((((unsigned)b0) >> 10) == tag) &&
                           ((((unsigned)b1) >> 10) == tag);
                if (__all_sync(0xFFFFFFFFu, okb)) { v0 = b0; v1 = b1; break; }
            }
            unsigned long long vm = (v0 < v1) ? v0 : v1;
            unsigned qhi = (unsigned)(vm >> 32), qlo = (unsigned)vm;
            unsigned gh = __reduce_min_sync(0xFFFFFFFFu, qhi);
            unsigned gc = (qhi == gh) ? qlo : 0xFFFFFFFFu;
            unsigned gl = __reduce_min_sync(0xFFFFFFFFu, gc);
            const int bmu = (int)(gl & 0x3FFu);

            // ---- (b) critical tail: c, ABV (ready long ago), store ----
            const float ci = c_table[lut_base - (bmu >> 5) * 63 - (bmu & 31)];
            if (t + 1 < TS) {
                bool ok;
                do {
                    ok = (lane >= NPC) || (sm_flag[lane] == t + 1);
                } while (!__all_sync(0xFFFFFFFFu, ok));
                __threadfence_block();
                const float4 q = sm_ABV[par][lane & 15];      // (A, -2B, V)
                float d2 = fmaxf(fmaf(ci, fmaf(ci, q.z, q.y), q.x), 0.f);
                unsigned tag2 = (unsigned)(t + 2) & 0x3FFFFFu;
                unsigned long long pk = (lane < NPC)
                    ? (((unsigned long long)__float_as_uint(d2) << 32)
                       | ((tag2 << 10) | (unsigned)nl))
                    : 0xFFFFFFFFFFFFFFFFull;
                unsigned phi2 = (unsigned)(pk >> 32), plo2 = (unsigned)pk;
                unsigned mhi2 = __reduce_min_sync(0xFFFFFFFFu, phi2);
                unsigned cnd2 = (phi2 == mhi2) ? plo2 : 0xFFFFFFFFu;
                unsigned mlo2 = __reduce_min_sync(0xFFFFFFFFu, cnd2);
                if (lane == 0)
                    st_rlx(&g_slots[(t + 1) & (RING - 1)][cta],
                           ((unsigned long long)mhi2 << 32) | mlo2);
            }
            // ---- (c) off-chain: publish c(t), then straight to next poll ----
            if (lane < NPC) sm_c[par][lane] = ci;
            __threadfence_block();
            if (lane == 0) sm_cflag = t + 1;
        }

        // ---- termination handshake + scratch cleanup (deterministic replays) ----
        // ring(TS&3) received no candidate store (skipped at t=TS-1), so the
        // handshake tag TS+1 is this slot's unique terminal value.
        const unsigned ftag = (unsigned)(TS + 1) & 0x3FFFFFu;
        const int fring = TS & (RING - 1);
        if (lane == 0)
            st_rlx(&g_slots[fring][cta], (unsigned long long)(ftag << 10));

        if (cta == 0) {
            for (;;) {
                unsigned long long v0 = ld_rlx(&g_slots[fring][lane]);
                unsigned long long v1 = ld_rlx(&g_slots[fring][lane + 32]);
                bool ok = ((((unsigned)v0) >> 10) == ftag) &&
                          ((((unsigned)v1) >> 10) == ftag);
                if (__all_sync(0xFFFFFFFFu, ok)) break;
            }
#pragma unroll
            for (int r = 0; r < RING; r++) {
                st_rlx(&g_slots[r][lane], 0ull);
                st_rlx(&g_slots[r][lane + 32], 0ull);
            }
            __threadfence();
        }
    } else {
        // =================== neuron warps: whole loop ===================
        for (int t = 0; t < TS; ++t) {
            const int par = t & 1;

            while (sm_cflag < t) { }             // c(t-1) published at cflag==t
            __threadfence_block();
            const float cp = sm_c[par ^ 1][warp];    // c(t-1)
#pragma unroll
            for (int k = 0; k < KREG; k++) {
                float vo = v[k];
                w[k] = fmaf(cp, vo, w[k]);
                v[k] = fmaf(-cp, vo, u[k]);
                u[k] = xn[k] - w[k];
            }
            const float* xp = X + (size_t)pf * DIM + lane;   // prefetch x(t+2)
#pragma unroll
            for (int k = 0; k < KREG; k++) xn[k] = xp[32 * k];
            pf++; if (pf == n_samples) pf = 0;

            float a0 = 0.f, a1 = 0.f, b0 = 0.f, b1 = 0.f, q0 = 0.f, q1 = 0.f;
#pragma unroll
            for (int k = 0; k < KREG; k += 2) {
                a0 = fmaf(u[k + 0], u[k + 0], a0); b0 = fmaf(u[k + 0], v[k + 0], b0);
                q0 = fmaf(v[k + 0], v[k + 0], q0);
                a1 = fmaf(u[k + 1], u[k + 1], a1); b1 = fmaf(u[k + 1], v[k + 1], b1);
                q1 = fmaf(v[k + 1], v[k + 1], q1);
            }
            float A = a0 + a1, B = b0 + b1, V = q0 + q1;
#pragma unroll
            for (int off = 16; off; off >>= 1) {
                A += __shfl_xor_sync(0xFFFFFFFFu, A, off);
                B += __shfl_xor_sync(0xFFFFFFFFu, B, off);
                V += __shfl_xor_sync(0xFFFFFFFFu, V, off);
            }
            if (lane == 0) {
                sm_ABV[par][warp] = make_float4(A, -2.f * B, V, 0.f);
                __threadfence_block();
                sm_flag[warp] = t + 1;               // ABV(t) ready
            }
        }

        // epilogue: apply final update c(TS-1), write weights
        while (sm_cflag < TS) { }
        __threadfence_block();
        const float cp = sm_c[(TS - 1) & 1][warp];
#pragma unroll
        for (int k = 0; k < KREG; k++)
            out[n * DIM + lane + 32 * k] = fmaf(cp, v[k], w[k]);
    }
}

extern "C" void kernel_launch(void* const* d_in, const int* in_sizes, int n_in,
                              void* d_out, int out_size)
{
    const float* X  = (const float*)d_in[0];   // [8192, 384]
    const float* W0 = (const float*)d_in[1];   // [32, 32, 384]
    const int*   ep = (const int*)d_in[3];     // num_epochs
    float* out = (float*)d_out;                // [32, 32, 384]

    int n_samples = in_sizes[0] / DIM;
    som_kernel<<<NCTA, NTHREADS>>>(X, W0, ep, out, n_samples);
}

// round 15
// speedup vs baseline: 1.3907x; 1.0577x over previous
#include <cuda_runtime.h>

// SOM batch_train, 8192 sequential steps. Persistent 64-CTA kernel:
// 16 neuron warps + 1 comm warp per CTA (544 thr).
// R15 delta vs R14 (8083us): (1) neuron spin-waits use __nanosleep backoff --
// 16 hot volatile-LDS spin loops were saturating SMSP issue + MIO exactly
// during the comm warp's critical tail (detect->redux->LUT->ABV->redux->store),
// stretching the inter-CTA chain; (2) poll deepened to 3 load pairs in flight.
// Everything else (protocol, arithmetic, flags, handshake) identical to R14.
//
//   d2_{t+1} = A - 2cB + c^2 V,  u=x_{t+1}-w_t, v=x_t-w_t, A=|u|^2,B=<u,v>,V=|v|^2
// All sums fresh each step (no drift). sm_c/sm_ABV double-buffered by parity.

#define DIM      384
#define KREG     12           // DIM / 32 dims per lane
#define NCTA     64
#define NPC      16           // neurons per CTA
#define NTHREADS 544          // 16 neuron warps + 1 comm warp
#define RING     4

// packed (d2bits:32 | tag:22 | neuron:10); zero at load, re-zeroed each launch
__device__ unsigned long long g_slots[RING][NCTA];

static __device__ __forceinline__ unsigned long long ld_rlx(const unsigned long long* p) {
    unsigned long long v;
    asm volatile("ld.relaxed.gpu.global.b64 %0, [%1];" : "=l"(v) : "l"(p) : "memory");
    return v;
}
static __device__ __forceinline__ void st_rlx(unsigned long long* p, unsigned long long v) {
    asm volatile("st.relaxed.gpu.global.b64 [%0], %1;" :: "l"(p), "l"(v) : "memory");
}

__global__ void __launch_bounds__(NTHREADS, 1)
som_kernel(const float* __restrict__ X, const float* __restrict__ W0,
           const int* __restrict__ ep, float* __restrict__ out, int n_samples)
{
    const int cta  = blockIdx.x;
    const int tid  = threadIdx.x;
    const int warp = tid >> 5;
    const int lane = tid & 31;

    int epochs = *ep;
    if (epochs < 1 || epochs > 8) epochs = 1;
    const int TS = epochs * n_samples;           // <= 65536, tags fit 22 bits

    __shared__ float c_table[63 * 63];           // 0.1*exp(-0.5*sqrt(dx^2+dy^2))
    __shared__ float4 sm_ABV[2][NPC];            // (A, -2B, V), parity-buffered
    __shared__ float sm_c[2][NPC];               // per-neuron c, parity-buffered
    __shared__ volatile int sm_flag[NPC];        // ABV-ready tag per neuron warp
    __shared__ volatile int sm_cflag;            // c-ready tag from comm warp
    __shared__ unsigned long long sm_pack[NPC];  // prologue only

    for (int i = tid; i < 63 * 63; i += NTHREADS) {
        float dx = (float)(i / 63 - 31);
        float dy = (float)(i % 63 - 31);
        c_table[i] = 0.1f * expf(-0.5f * sqrtf(dx * dx + dy * dy));
    }
    if (tid < NPC) { sm_c[1][tid] = 0.f; sm_flag[tid] = 0; }
    if (tid == 0) sm_cflag = 0;

    // ---- neuron-warp state ----
    const int n = cta * NPC + warp;              // valid for warp < 16
    float w[KREG], v[KREG], u[KREG], xn[KREG];
    int pf = (n_samples > 2) ? 2 : (2 % n_samples);

    if (warp < NPC) {
        float a0 = 0.f, a1 = 0.f, a2 = 0.f, a3 = 0.f;
#pragma unroll
        for (int k = 0; k < KREG; k++) {
            float wk = W0[n * DIM + lane + 32 * k];
            w[k] = wk;
            v[k] = 0.f;
            float t0 = X[lane + 32 * k] - wk;    // u = x0 - w0
            u[k] = t0;
            if ((k & 3) == 0) a0 = fmaf(t0, t0, a0);
            else if ((k & 3) == 1) a1 = fmaf(t0, t0, a1);
            else if ((k & 3) == 2) a2 = fmaf(t0, t0, a2);
            else a3 = fmaf(t0, t0, a3);
        }
        float d2 = (a0 + a1) + (a2 + a3);
#pragma unroll
        for (int off = 16; off; off >>= 1)
            d2 += __shfl_xor_sync(0xFFFFFFFFu, d2, off);
#pragma unroll
        for (int k = 0; k < KREG; k++) xn[k] = X[DIM + lane + 32 * k];   // x1

        if (lane == 0)
            sm_pack[warp] = ((unsigned long long)__float_as_uint(d2) << 32)
                          | ((1u << 10) | (unsigned)n);
    }

    __syncthreads();     // prologue only: packs + sm_c[1] + flags + LUT visible

    if (warp == NPC) {                           // store candidate(0), tag 1
        unsigned long long p = (lane < NPC) ? sm_pack[lane] : 0xFFFFFFFFFFFFFFFFull;
        unsigned phi = (unsigned)(p >> 32), plo = (unsigned)p;
        unsigned mhi = __reduce_min_sync(0xFFFFFFFFu, phi);
        unsigned cnd = (phi == mhi) ? plo : 0xFFFFFFFFu;
        unsigned mlo = __reduce_min_sync(0xFFFFFFFFu, cnd);
        if (lane == 0)
            st_rlx(&g_slots[0][cta], ((unsigned long long)mhi << 32) | mlo);
    }

    const int nl = cta * NPC + (lane & 15);      // comm-lane neuron id (in range)
    const int lut_base = (nl >> 5) * 63 + (nl & 31) + (31 * 63 + 31);

    if (warp == NPC) {
        // =================== comm warp: whole loop ===================
        for (int t = 0; t < TS; ++t) {
            const int par = t & 1;

            // ---- (a) 3-deep pipelined, coalesced L2 poll for bmu(t) ----
            const unsigned tag = (unsigned)(t + 1) & 0x3FFFFFu;
            const int ring = t & (RING - 1);
            unsigned long long* p0 = &g_slots[ring][lane];
            unsigned long long* p1 = &g_slots[ring][lane + 32];
            unsigned long long v0, v1;
            for (;;) {
                unsigned long long a0 = ld_rlx(p0), a1 = ld_rlx(p1);
                unsigned long long b0 = ld_rlx(p0), b1 = ld_rlx(p1);
                unsigned long long c0 = ld_rlx(p0), c1 = ld_rlx(p1);
                bool oka = ((((unsigned)a0) >> 10) == tag) &&
                           ((((unsigned)a1) >> 10) == tag);
                if (__all_sync(0xFFFFFFFFu, oka)) { v0 = a0; v1 = a1; break; }
                bool okb = ((((unsigned)b0) >> 10) == tag) &&
                           ((((unsigned)b1) >> 10) == tag);
                if (__all_sync(0xFFFFFFFFu, okb)) { v0 = b0; v1 = b1; break; }
                bool okc = ((((unsigned)c0) >> 10) == tag) &&
                           ((((unsigned)c1) >> 10) == tag);
                if (__all_sync(0xFFFFFFFFu, okc)) { v0 = c0; v1 = c1; break; }
            }
            unsigned long long vm = (v0 < v1) ? v0 : v1;
            unsigned qhi = (unsigned)(vm >> 32), qlo = (unsigned)vm;
            unsigned gh = __reduce_min_sync(0xFFFFFFFFu, qhi);
            unsigned gc = (qhi == gh) ? qlo : 0xFFFFFFFFu;
            unsigned gl = __reduce_min_sync(0xFFFFFFFFu, gc);
            const int bmu = (int)(gl & 0x3FFu);

            // ---- (b) critical tail: c, ABV (ready long ago), store ----
            const float ci = c_table[lut_base - (bmu >> 5) * 63 - (bmu & 31)];
            if (t + 1 < TS) {
                bool ok;
                do {
                    ok = (lane >= NPC) || (sm_flag[lane] == t + 1);
                } while (!__all_sync(0xFFFFFFFFu, ok));
                __threadfence_block();
                const float4 q = sm_ABV[par][lane & 15];      // (A, -2B, V)
                float d2 = fmaxf(fmaf(ci, fmaf(ci, q.z, q.y), q.x), 0.f);
                unsigned tag2 = (unsigned)(t + 2) & 0x3FFFFFu;
                unsigned long long pk = (lane < NPC)
                    ? (((unsigned long long)__float_as_uint(d2) << 32)
                       | ((tag2 << 10) | (unsigned)nl))
                    : 0xFFFFFFFFFFFFFFFFull;
                unsigned phi2 = (unsigned)(pk >> 32), plo2 = (unsigned)pk;
                unsigned mhi2 = __reduce_min_sync(0xFFFFFFFFu, phi2);
                unsigned cnd2 = (phi2 == mhi2) ? plo2 : 0xFFFFFFFFu;
                unsigned mlo2 = __reduce_min_sync(0xFFFFFFFFu, cnd2);
                if (lane == 0)
                    st_rlx(&g_slots[(t + 1) & (RING - 1)][cta],
                           ((unsigned long long)mhi2 << 32) | mlo2);
            }
            // ---- (c) off-chain: publish c(t), then straight to next poll ----
            if (lane < NPC) sm_c[par][lane] = ci;
            __threadfence_block();
            if (lane == 0) sm_cflag = t + 1;
        }

        // ---- termination handshake + scratch cleanup (deterministic replays) ----
        // ring(TS&3) received no candidate store (skipped at t=TS-1), so the
        // handshake tag TS+1 is this slot's unique terminal value.
        const unsigned ftag = (unsigned)(TS + 1) & 0x3FFFFFu;
        const int fring = TS & (RING - 1);
        if (lane == 0)
            st_rlx(&g_slots[fring][cta], (unsigned long long)(ftag << 10));

        if (cta == 0) {
            for (;;) {
                unsigned long long v0 = ld_rlx(&g_slots[fring][lane]);
                unsigned long long v1 = ld_rlx(&g_slots[fring][lane + 32]);
                bool ok = ((((unsigned)v0) >> 10) == ftag) &&
                          ((((unsigned)v1) >> 10) == ftag);
                if (__all_sync(0xFFFFFFFFu, ok)) break;
            }
#pragma unroll
            for (int r = 0; r < RING; r++) {
                st_rlx(&g_slots[r][lane], 0ull);
                st_rlx(&g_slots[r][lane + 32], 0ull);
            }
            __threadfence();
        }
    } else {
        // =================== neuron warps: whole loop ===================
        for (int t = 0; t < TS; ++t) {
            const int par = t & 1;

            // polite spin: c(t-1) published at cflag==t. Hot volatile-LDS spin
            // here was saturating SMSP issue/MIO during the comm tail (R14).
            if (sm_cflag < t) {
                do { __nanosleep(40); } while (sm_cflag < t);
            }
            __threadfence_block();
            const float cp = sm_c[par ^ 1][warp];    // c(t-1)
#pragma unroll
            for (int k = 0; k < KREG; k++) {
                float vo = v[k];
                w[k] = fmaf(cp, vo, w[k]);
                v[k] = fmaf(-cp, vo, u[k]);
                u[k] = xn[k] - w[k];
            }
            const float* xp = X + (size_t)pf * DIM + lane;   // prefetch x(t+2)
#pragma unroll
            for (int k = 0; k < KREG; k++) xn[k] = xp[32 * k];
            pf++; if (pf == n_samples) pf = 0;

            float a0 = 0.f, a1 = 0.f, b0 = 0.f, b1 = 0.f, q0 = 0.f, q1 = 0.f;
#pragma unroll
            for (int k = 0; k < KREG; k += 2) {
                a0 = fmaf(u[k + 0], u[k + 0], a0); b0 = fmaf(u[k + 0], v[k + 0], b0);
                q0 = fmaf(v[k + 0], v[k + 0], q0);
                a1 = fmaf(u[k + 1], u[k + 1], a1); b1 = fmaf(u[k + 1], v[k + 1], b1);
                q1 = fmaf(v[k + 1], v[k + 1], q1);
            }
            float A = a0 + a1, B = b0 + b1, V = q0 + q1;
#pragma unroll
            for (int off = 16; off; off >>= 1) {
                A += __shfl_xor_sync(0xFFFFFFFFu, A, off);
                B += __shfl_xor_sync(0xFFFFFFFFu, B, off);
                V += __shfl_xor_sync(0xFFFFFFFFu, V, off);
            }
            if (lane == 0) {
                sm_ABV[par][warp] = make_float4(A, -2.f * B, V, 0.f);
                __threadfence_block();
                sm_flag[warp] = t + 1;               // ABV(t) ready
            }
        }

        // epilogue: apply final update c(TS-1), write weights
        if (sm_cflag < TS) {
            do { __nanosleep(40); } while (sm_cflag < TS);
        }
        __threadfence_block();
        const float cp = sm_c[(TS - 1) & 1][warp];
#pragma unroll
        for (int k = 0; k < KREG; k++)
            out[n * DIM + lane + 32 * k] = fmaf(cp, v[k], w[k]);
    }
}

extern "C" void kernel_launch(void* const* d_in, const int* in_sizes, int n_in,
                              void* d_out, int out_size)
{
    const float* X  = (const float*)d_in[0];   // [8192, 384]
    const float* W0 = (const float*)d_in[1];   // [32, 32, 384]
    const int*   ep = (const int*)d_in[3];     // num_epochs
    float* out = (float*)d_out;                // [32, 32, 384]

    int n_samples = in_sizes[0] / DIM;
    som_kernel<<<NCTA, NTHREADS>>>(X, W0, ep, out, n_samples);
}

// round 16
// speedup vs baseline: 1.4340x; 1.0311x over previous
#include <cuda_runtime.h>

// SOM batch_train, 8192 sequential steps. Persistent 64-CTA kernel:
// 16 neuron warps + 1 comm warp per CTA (544 thr).
// R16 delta vs R15 (7642us): SOFTWARE-PIPELINED poll. Previous polls issued
// all loads in one burst then blocked ~260cyc -> slots sampled every ~290cyc,
// detection lag ~400cyc. Now each iteration issues a fresh pair and checks the
// pair issued LAST iteration (already landed): sampling interval ~= loop body
// (~50cyc), detection lag ~= one load latency (~290cyc). Everything else
// (protocol, nanosleep backoff, tail order, flags, handshake) identical to R15.
//
//   d2_{t+1} = A - 2cB + c^2 V,  u=x_{t+1}-w_t, v=x_t-w_t, A=|u|^2,B=<u,v>,V=|v|^2
// All sums fresh each step (no drift). sm_c/sm_ABV double-buffered by parity.

#define DIM      384
#define KREG     12           // DIM / 32 dims per lane
#define NCTA     64
#define NPC      16           // neurons per CTA
#define NTHREADS 544          // 16 neuron warps + 1 comm warp
#define RING     4

// packed (d2bits:32 | tag:22 | neuron:10); zero at load, re-zeroed each launch
__device__ unsigned long long g_slots[RING][NCTA];

static __device__ __forceinline__ unsigned long long ld_rlx(const unsigned long long* p) {
    unsigned long long v;
    asm volatile("ld.relaxed.gpu.global.b64 %0, [%1];" : "=l"(v) : "l"(p) : "memory");
    return v;
}
static __device__ __forceinline__ void st_rlx(unsigned long long* p, unsigned long long v) {
    asm volatile("st.relaxed.gpu.global.b64 [%0], %1;" :: "l"(p), "l"(v) : "memory");
}

__global__ void __launch_bounds__(NTHREADS, 1)
som_kernel(const float* __restrict__ X, const float* __restrict__ W0,
           const int* __restrict__ ep, float* __restrict__ out, int n_samples)
{
    const int cta  = blockIdx.x;
    const int tid  = threadIdx.x;
    const int warp = tid >> 5;
    const int lane = tid & 31;

    int epochs = *ep;
    if (epochs < 1 || epochs > 8) epochs = 1;
    const int TS = epochs * n_samples;           // <= 65536, tags fit 22 bits

    __shared__ float c_table[63 * 63];           // 0.1*exp(-0.5*sqrt(dx^2+dy^2))
    __shared__ float4 sm_ABV[2][NPC];            // (A, -2B, V), parity-buffered
    __shared__ float sm_c[2][NPC];               // per-neuron c, parity-buffered
    __shared__ volatile int sm_flag[NPC];        // ABV-ready tag per neuron warp
    __shared__ volatile int sm_cflag;            // c-ready tag from comm warp
    __shared__ unsigned long long sm_pack[NPC];  // prologue only

    for (int i = tid; i < 63 * 63; i += NTHREADS) {
        float dx = (float)(i / 63 - 31);
        float dy = (float)(i % 63 - 31);
        c_table[i] = 0.1f * expf(-0.5f * sqrtf(dx * dx + dy * dy));
    }
    if (tid < NPC) { sm_c[1][tid] = 0.f; sm_flag[tid] = 0; }
    if (tid == 0) sm_cflag = 0;

    // ---- neuron-warp state ----
    const int n = cta * NPC + warp;              // valid for warp < 16
    float w[KREG], v[KREG], u[KREG], xn[KREG];
    int pf = (n_samples > 2) ? 2 : (2 % n_samples);

    if (warp < NPC) {
        float a0 = 0.f, a1 = 0.f, a2 = 0.f, a3 = 0.f;
#pragma unroll
        for (int k = 0; k < KREG; k++) {
            float wk = W0[n * DIM + lane + 32 * k];
            w[k] = wk;
            v[k] = 0.f;
            float t0 = X[lane + 32 * k] - wk;    // u = x0 - w0
            u[k] = t0;
            if ((k & 3) == 0) a0 = fmaf(t0, t0, a0);
            else if ((k & 3) == 1) a1 = fmaf(t0, t0, a1);
            else if ((k & 3) == 2) a2 = fmaf(t0, t0, a2);
            else a3 = fmaf(t0, t0, a3);
        }
        float d2 = (a0 + a1) + (a2 + a3);
#pragma unroll
        for (int off = 16; off; off >>= 1)
            d2 += __shfl_xor_sync(0xFFFFFFFFu, d2, off);
#pragma unroll
        for (int k = 0; k < KREG; k++) xn[k] = X[DIM + lane + 32 * k];   // x1

        if (lane == 0)
            sm_pack[warp] = ((unsigned long long)__float_as_uint(d2) << 32)
                          | ((1u << 10) | (unsigned)n);
    }

    __syncthreads();     // prologue only: packs + sm_c[1] + flags + LUT visible

    if (warp == NPC) {                           // store candidate(0), tag 1
        unsigned long long p = (lane < NPC) ? sm_pack[lane] : 0xFFFFFFFFFFFFFFFFull;
        unsigned phi = (unsigned)(p >> 32), plo = (unsigned)p;
        unsigned mhi = __reduce_min_sync(0xFFFFFFFFu, phi);
        unsigned cnd = (phi == mhi) ? plo : 0xFFFFFFFFu;
        unsigned mlo = __reduce_min_sync(0xFFFFFFFFu, cnd);
        if (lane == 0)
            st_rlx(&g_slots[0][cta], ((unsigned long long)mhi << 32) | mlo);
    }

    const int nl = cta * NPC + (lane & 15);      // comm-lane neuron id (in range)
    const int lut_base = (nl >> 5) * 63 + (nl & 31) + (31 * 63 + 31);

    if (warp == NPC) {
        // =================== comm warp: whole loop ===================
        for (int t = 0; t < TS; ++t) {
            const int par = t & 1;

            // ---- (a) software-pipelined poll for bmu(t): check the pair
            //      issued LAST iteration while a fresh pair is in flight ----
            const unsigned tag = (unsigned)(t + 1) & 0x3FFFFFu;
            const int ring = t & (RING - 1);
            unsigned long long* p0 = &g_slots[ring][lane];
            unsigned long long* p1 = &g_slots[ring][lane + 32];
            unsigned long long v0, v1;
            {
                unsigned long long a0 = ld_rlx(p0), a1 = ld_rlx(p1);
                for (;;) {
                    unsigned long long b0 = ld_rlx(p0), b1 = ld_rlx(p1);
                    bool ok = ((((unsigned)a0) >> 10) == tag) &&
                              ((((unsigned)a1) >> 10) == tag);
                    if (__all_sync(0xFFFFFFFFu, ok)) { v0 = a0; v1 = a1; break; }
                    a0 = b0; a1 = b1;
                }
            }
            unsigned long long vm = (v0 < v1) ? v0 : v1;
            unsigned qhi = (unsigned)(vm >> 32), qlo = (unsigned)vm;
            unsigned gh = __reduce_min_sync(0xFFFFFFFFu, qhi);
            unsigned gc = (qhi == gh) ? qlo : 0xFFFFFFFFu;
            unsigned gl = __reduce_min_sync(0xFFFFFFFFu, gc);
            const int bmu = (int)(gl & 0x3FFu);

            // ---- (b) critical tail: c, ABV (ready long ago), store ----
            const float ci = c_table[lut_base - (bmu >> 5) * 63 - (bmu & 31)];
            if (t + 1 < TS) {
                bool ok;
                do {
                    ok = (lane >= NPC) || (sm_flag[lane] == t + 1);
                } while (!__all_sync(0xFFFFFFFFu, ok));
                __threadfence_block();
                const float4 q = sm_ABV[par][lane & 15];      // (A, -2B, V)
                float d2 = fmaxf(fmaf(ci, fmaf(ci, q.z, q.y), q.x), 0.f);
                unsigned tag2 = (unsigned)(t + 2) & 0x3FFFFFu;
                unsigned long long pk = (lane < NPC)
                    ? (((unsigned long long)__float_as_uint(d2) << 32)
                       | ((tag2 << 10) | (unsigned)nl))
                    : 0xFFFFFFFFFFFFFFFFull;
                unsigned phi2 = (unsigned)(pk >> 32), plo2 = (unsigned)pk;
                unsigned mhi2 = __reduce_min_sync(0xFFFFFFFFu, phi2);
                unsigned cnd2 = (phi2 == mhi2) ? plo2 : 0xFFFFFFFFu;
                unsigned mlo2 = __reduce_min_sync(0xFFFFFFFFu, cnd2);
                if (lane == 0)
                    st_rlx(&g_slots[(t + 1) & (RING - 1)][cta],
                           ((unsigned long long)mhi2 << 32) | mlo2);
            }
            // ---- (c) off-chain: publish c(t), then straight to next poll ----
            if (lane < NPC) sm_c[par][lane] = ci;
            __threadfence_block();
            if (lane == 0) sm_cflag = t + 1;
        }

        // ---- termination handshake + scratch cleanup (deterministic replays) ----
        // ring(TS&3) received no candidate store (skipped at t=TS-1), so the
        // handshake tag TS+1 is this slot's unique terminal value.
        const unsigned ftag = (unsigned)(TS + 1) & 0x3FFFFFu;
        const int fring = TS & (RING - 1);
        if (lane == 0)
            st_rlx(&g_slots[fring][cta], (unsigned long long)(ftag << 10));

        if (cta == 0) {
            for (;;) {
                unsigned long long v0 = ld_rlx(&g_slots[fring][lane]);
                unsigned long long v1 = ld_rlx(&g_slots[fring][lane + 32]);
                bool ok = ((((unsigned)v0) >> 10) == ftag) &&
                          ((((unsigned)v1) >> 10) == ftag);
                if (__all_sync(0xFFFFFFFFu, ok)) break;
            }
#pragma unroll
            for (int r = 0; r < RING; r++) {
                st_rlx(&g_slots[r][lane], 0ull);
                st_rlx(&g_slots[r][lane + 32], 0ull);
            }
            __threadfence();
        }
    } else {
        // =================== neuron warps: whole loop ===================
        for (int t = 0; t < TS; ++t) {
            const int par = t & 1;

            // polite spin with nanosleep backoff (R15: keeps SMSP issue free
            // for the comm warp's critical tail)
            if (sm_cflag < t) {
                do { __nanosleep(40); } while (sm_cflag < t);
            }
            __threadfence_block();
            const float cp = sm_c[par ^ 1][warp];    // c(t-1)
#pragma unroll
            for (int k = 0; k < KREG; k++) {
                float vo = v[k];
                w[k] = fmaf(cp, vo, w[k]);
                v[k] = fmaf(-cp, vo, u[k]);
                u[k] = xn[k] - w[k];
            }
            const float* xp = X + (size_t)pf * DIM + lane;   // prefetch x(t+2)
#pragma unroll
            for (int k = 0; k < KREG; k++) xn[k] = xp[32 * k];
            pf++; if (pf == n_samples) pf = 0;

            float a0 = 0.f, a1 = 0.f, b0 = 0.f, b1 = 0.f, q0 = 0.f, q1 = 0.f;
#pragma unroll
            for (int k = 0; k < KREG; k += 2) {
                a0 = fmaf(u[k + 0], u[k + 0], a0); b0 = fmaf(u[k + 0], v[k + 0], b0);
                q0 = fmaf(v[k + 0], v[k + 0], q0);
                a1 = fmaf(u[k + 1], u[k + 1], a1); b1 = fmaf(u[k + 1], v[k + 1], b1);
                q1 = fmaf(v[k + 1], v[k + 1], q1);
            }
            float A = a0 + a1, B = b0 + b1, V = q0 + q1;
#pragma unroll
            for (int off = 16; off; off >>= 1) {
                A += __shfl_xor_sync(0xFFFFFFFFu, A, off);
                B += __shfl_xor_sync(0xFFFFFFFFu, B, off);
                V += __shfl_xor_sync(0xFFFFFFFFu, V, off);
            }
            if (lane == 0) {
                sm_ABV[par][warp] = make_float4(A, -2.f * B, V, 0.f);
                __threadfence_block();
                sm_flag[warp] = t + 1;               // ABV(t) ready
            }
        }

        // epilogue: apply final update c(TS-1), write weights
        if (sm_cflag < TS) {
            do { __nanosleep(40); } while (sm_cflag < TS);
        }
        __threadfence_block();
        const float cp = sm_c[(TS - 1) & 1][warp];
#pragma unroll
        for (int k = 0; k < KREG; k++)
            out[n * DIM + lane + 32 * k] = fmaf(cp, v[k], w[k]);
    }
}

extern "C" void kernel_launch(void* const* d_in, const int* in_sizes, int n_in,
                              void* d_out, int out_size)
{
    const float* X  = (const float*)d_in[0];   // [8192, 384]
    const float* W0 = (const float*)d_in[1];   // [32, 32, 384]
    const int*   ep = (const int*)d_in[3];     // num_epochs
    float* out = (float*)d_out;                // [32, 32, 384]

    int n_samples = in_sizes[0] / DIM;
    som_kernel<<<NCTA, NTHREADS>>>(X, W0, ep, out, n_samples);
}